// round 13
// baseline (speedup 1.0000x reference)
#include <cuda_runtime.h>
#include <cuda_bf16.h>

#define BATCH  32
#define LSEQ   1025
#define NTOK   513
#define TLEN   2048
#define EMB    384
#define VOCAB  100
#define TT     16            // frames per tile
#define NTILES (TLEN / TT)   // 128
#define KMAX   64            // max tokens per tile list
#define PWARPS 17            // prep warps (544 threads)

#define NSG    3             // subgroups per block
#define SGT    192           // threads per subgroup (2 cols each)
#define NTH    (NSG * SGT)   // 576
#define GRID   148           // persistent: 1 CTA per SM
#define STREAMS (GRID * NSG) // 444 independent tile streams
#define TOTAL  (BATCH * NTILES)

#define TABF   (VOCAB * EMB)         // 38400 floats
#define AREA   1344                  // floats per subgroup scratch area
#define SMEMF  (TABF + NSG * AREA)   // total dynamic smem floats
#define SMEMB  (SMEMF * 4)

using u64 = unsigned long long;

__device__ float4 g_list[BATCH][NTILES][KMAX]; // compacted per-tile token params
__device__ int    g_cnt[BATCH][NTILES];
__device__ float  g_cumend[BATCH];

__device__ __forceinline__ u64 pack2(float lo, float hi) {
    u64 r; asm("mov.b64 %0, {%1,%2};" : "=l"(r) : "f"(lo), "f"(hi)); return r;
}
__device__ __forceinline__ void unpack2(u64 v, float& lo, float& hi) {
    asm("mov.b64 {%0,%1}, %2;" : "=f"(lo), "=f"(hi) : "l"(v));
}
__device__ __forceinline__ u64 ffma2(u64 a, u64 b, u64 c) {
    u64 r; asm("fma.rn.f32x2 %0, %1, %2, %3;" : "=l"(r) : "l"(a), "l"(b), "l"(c)); return r;
}
__device__ __forceinline__ u64 fmul2(u64 a, u64 b) {
    u64 r; asm("mul.rn.f32x2 %0, %1, %2;" : "=l"(r) : "l"(a), "l"(b)); return r;
}
__device__ __forceinline__ void sgbar(int s) {
    asm volatile("bar.sync %0, %1;" :: "r"(s + 1), "r"(SGT) : "memory");
}

// ---------------- Kernel A: merge + warp-shuffle scan + per-tile compacted lists ----------------
__global__ void prep_kernel(const int* __restrict__ text, const int* __restrict__ durs) {
    const int b    = blockIdx.x;
    const int i    = threadIdx.x;
    const int lane = i & 31;
    const int wid  = i >> 5;

    __shared__ float wpart[PWARPS];
    __shared__ int   s_cnt[NTILES];

    if (i < NTILES) s_cnt[i] = 0;

    float d = 0.0f; int tx = 0;
    if (i < NTOK) {
        if (i == 0) { d = (float)durs[b * LSEQ]; tx = text[b * LSEQ]; }
        else {
            d  = (float)(durs[b * LSEQ + 2 * i - 1] + durs[b * LSEQ + 2 * i]);
            tx = text[b * LSEQ + 2 * i - 1];
        }
    }

    // warp-level inclusive scan
    float v = d;
#pragma unroll
    for (int off = 1; off < 32; off <<= 1) {
        float n = __shfl_up_sync(0xffffffffu, v, off);
        if (lane >= off) v += n;
    }
    if (lane == 31) wpart[wid] = v;
    __syncthreads();            // also orders s_cnt zeroing before appends
    if (wid == 0) {
        float s = (lane < PWARPS) ? wpart[lane] : 0.0f;
#pragma unroll
        for (int off = 1; off < 32; off <<= 1) {
            float n = __shfl_up_sync(0xffffffffu, s, off);
            if (lane >= off) s += n;
        }
        if (lane < PWARPS) wpart[lane] = s;
    }
    __syncthreads();
    const float cum = v + (wid > 0 ? wpart[wid - 1] : 0.0f);

    if (i < NTOK) {
        float c    = cum - 0.5f * d;
        float sig  = 0.5f * d + 1e-6f;
        float invs = 1.0f / sig;
        bool  kept = (tx != 0) && (d > 0.0f);
        if (kept) {
            float coef = 0.3989422804014327f * invs;
            // z-cut = 5.5: dropped weights <= 2e-7 vs wsum >= 0.08 -> rel pert <= ~5e-5
            float r = 2.75f * d + 0.51f;
            int k0 = max(0, (int)ceilf((c - r - ((float)TT - 0.5f)) * (1.0f / TT)));
            int k1 = min(NTILES - 1, (int)floorf((c + r - 0.5f) * (1.0f / TT)));
            float4 e = make_float4(c, invs, coef, __int_as_float(tx));
            for (int k = k0; k <= k1; ++k) {
                int s = atomicAdd(&s_cnt[k], 1);   // fast smem atomic
                if (s < KMAX) g_list[b][k][s] = e; // fire-and-forget STG.128
            }
        }
        if (i == NTOK - 1) g_cumend[b] = cum;
    }
    __syncthreads();
    if (i < NTILES) g_cnt[b][i] = min(s_cnt[i], KMAX);
}

// ---------------- Kernel B: persistent, table-in-smem, 3 independent subgroups ----------------
__global__ void __launch_bounds__(NTH, 1)
gauss_kernel(const float* __restrict__ emb, float* __restrict__ out) {
    extern __shared__ __align__(16) float smem[];
    const int tid = threadIdx.x;
    const int s   = tid / SGT;         // subgroup 0..2
    const int ts  = tid - s * SGT;     // owns embedding cols 2*ts, 2*ts+1

    // ---- stage whole embedding table into smem ----
    {
        const float4* emb4 = (const float4*)emb;
        float4* tab4 = (float4*)smem;
        for (int i = tid; i < TABF / 4; i += NTH) tab4[i] = emb4[i];
    }
    __syncthreads();

    const float* tab = smem;
    float* area   = smem + TABF + s * AREA;
    float* w_s    = area;               // [KMAX][TT] = 1024 floats
    float* s_c    = area + 1024;
    float* s_is   = area + 1088;
    float* s_cf   = area + 1152;
    int*   s_tok  = (int*)(area + 1216);
    float* wsum   = area + 1280;
    float* scale_s= area + 1296;

    float2* outp = reinterpret_cast<float2*>(out);

    // ---- prefetch first tile's count + list entry ----
    const int sgid = blockIdx.x * NSG + s;
    int cnt_next = 0;
    float4 p_next = make_float4(0.f, 0.f, 0.f, 0.f);
    {
        const int bb = sgid >> 7, kk = sgid & (NTILES - 1);
        cnt_next = g_cnt[bb][kk];
        if (ts < KMAX) p_next = g_list[bb][kk][ts];
    }

    for (int g = sgid; g < TOTAL; g += STREAMS) {
        const int b   = g >> 7;
        const int t0  = (g & (NTILES - 1)) * TT;
        const int cnt = min(cnt_next, KMAX);
        const float4 p = p_next;

        sgbar(s);    // previous tile fully done with this subgroup's smem
        if (ts < TT) wsum[ts] = 0.0f;
        if (ts < cnt) {
            s_c[ts]   = p.x;
            s_is[ts]  = p.y;
            s_cf[ts]  = p.z;
            s_tok[ts] = __float_as_int(p.w);
        }
        sgbar(s);

        // ---- issue next tile's loads (hidden behind this tile's compute) ----
        {
            const int gn = g + STREAMS;
            if (gn < TOTAL) {
                const int bn = gn >> 7, kn = gn & (NTILES - 1);
                cnt_next = g_cnt[bn][kn];
                if (ts < KMAX) p_next = g_list[bn][kn][ts];
            }
        }

        // ---- phase 1: weights -> smem; per-thread register wsum (frame = ts & 15) ----
        {
            const int   myt = ts & (TT - 1);
            const float tm  = (float)(t0 + myt) + 0.5f;
            float wl = 0.0f;
            for (int idx = ts; idx < cnt * TT; idx += SGT) {
                int nl = idx >> 4;
                float z = (tm - s_c[nl]) * s_is[nl];
                float w = s_cf[nl] * __expf(-0.5f * z * z);
                w_s[nl * TT + myt] = w;
                wl += w;
            }
            if (wl != 0.0f) atomicAdd(&wsum[myt], wl);
        }
        sgbar(s);

        if (ts < TT) {
            float tmv = (float)(t0 + ts) + 0.5f;
            scale_s[ts] = (tmv < g_cumend[b]) ? (1.0f / (wsum[ts] + 1e-6f)) : 0.0f;
        }

        // ---- phase 2: packed f32x2 accumulation; emb rows come from smem table ----
        u64 accA[TT / 2], accB[TT / 2];
#pragma unroll
        for (int j = 0; j < TT / 2; ++j) { accA[j] = 0ull; accB[j] = 0ull; }

        int cs = 0;
        for (; cs + 4 <= cnt; cs += 4) {
            float2 e0 = *(const float2*)&tab[s_tok[cs + 0] * EMB + 2 * ts];
            float2 e1 = *(const float2*)&tab[s_tok[cs + 1] * EMB + 2 * ts];
            float2 e2 = *(const float2*)&tab[s_tok[cs + 2] * EMB + 2 * ts];
            float2 e3 = *(const float2*)&tab[s_tok[cs + 3] * EMB + 2 * ts];
#pragma unroll
            for (int u = 0; u < 4; ++u) {
                float2 ev = (u == 0) ? e0 : (u == 1) ? e1 : (u == 2) ? e2 : e3;
                u64 exA = pack2(ev.x, ev.x);
                u64 exB = pack2(ev.y, ev.y);
                const ulonglong2* wp = reinterpret_cast<const ulonglong2*>(&w_s[(cs + u) * TT]);
#pragma unroll
                for (int j = 0; j < TT / 4; ++j) {
                    ulonglong2 wq = wp[j];
                    accA[2 * j + 0] = ffma2(wq.x, exA, accA[2 * j + 0]);
                    accB[2 * j + 0] = ffma2(wq.x, exB, accB[2 * j + 0]);
                    accA[2 * j + 1] = ffma2(wq.y, exA, accA[2 * j + 1]);
                    accB[2 * j + 1] = ffma2(wq.y, exB, accB[2 * j + 1]);
                }
            }
        }
        for (; cs < cnt; ++cs) {
            float2 ev = *(const float2*)&tab[s_tok[cs] * EMB + 2 * ts];
            u64 exA = pack2(ev.x, ev.x);
            u64 exB = pack2(ev.y, ev.y);
            const ulonglong2* wp = reinterpret_cast<const ulonglong2*>(&w_s[cs * TT]);
#pragma unroll
            for (int j = 0; j < TT / 4; ++j) {
                ulonglong2 wq = wp[j];
                accA[2 * j + 0] = ffma2(wq.x, exA, accA[2 * j + 0]);
                accB[2 * j + 0] = ffma2(wq.x, exB, accB[2 * j + 0]);
                accA[2 * j + 1] = ffma2(wq.y, exA, accA[2 * j + 1]);
                accB[2 * j + 1] = ffma2(wq.y, exB, accB[2 * j + 1]);
            }
        }
        sgbar(s);   // scale_s ready

        // ---- normalize (packed) + store (float2 per frame, coalesced) ----
        size_t base = ((size_t)g * TT) * (EMB / 2) + ts;   // b*TLEN + t0 == g*TT
        const u64* sp = reinterpret_cast<const u64*>(scale_s);
#pragma unroll
        for (int j = 0; j < TT / 2; ++j) {
            u64 s2 = sp[j];                      // (scale[2j], scale[2j+1])
            u64 va = fmul2(accA[j], s2);
            u64 vb = fmul2(accB[j], s2);
            float a0, a1, b0, b1;
            unpack2(va, a0, a1);
            unpack2(vb, b0, b1);
            outp[base + (size_t)(2 * j)     * (EMB / 2)] = make_float2(a0, b0);
            outp[base + (size_t)(2 * j + 1) * (EMB / 2)] = make_float2(a1, b1);
        }
    }
}

extern "C" void kernel_launch(void* const* d_in, const int* in_sizes, int n_in,
                              void* d_out, int out_size) {
    const int*   text = (const int*)d_in[0];
    const int*   durs = (const int*)d_in[1];
    const float* emb  = (const float*)d_in[2];
    float* out = (float*)d_out;

    cudaFuncSetAttribute(gauss_kernel, cudaFuncAttributeMaxDynamicSharedMemorySize, SMEMB);

    prep_kernel<<<BATCH, 544>>>(text, durs);
    gauss_kernel<<<GRID, NTH, SMEMB>>>(emb, out);
}

// round 14
// speedup vs baseline: 1.2942x; 1.2942x over previous
#include <cuda_runtime.h>
#include <cuda_bf16.h>

#define BATCH  32
#define LSEQ   1025
#define NTOK   513
#define TLEN   2048
#define EMB    384
#define TT     16            // frames per tile
#define NTILES (TLEN / TT)   // 128
#define NTH    192           // threads per block; each owns 2 embedding cols
#define KMAX   64            // max tokens per tile list
#define PWARPS 17            // prep warps (544 threads)
#define GBLK   592           // persistent grid: 4 CTAs/SM x 148 SMs
#define TOTAL  (BATCH * NTILES)

using u64 = unsigned long long;

__device__ float4 g_list[BATCH][NTILES][KMAX]; // compacted per-tile token params
__device__ int    g_cnt[BATCH][NTILES];
__device__ float  g_cumend[BATCH];

__device__ __forceinline__ u64 pack2(float lo, float hi) {
    u64 r; asm("mov.b64 %0, {%1,%2};" : "=l"(r) : "f"(lo), "f"(hi)); return r;
}
__device__ __forceinline__ void unpack2(u64 v, float& lo, float& hi) {
    asm("mov.b64 {%0,%1}, %2;" : "=f"(lo), "=f"(hi) : "l"(v));
}
__device__ __forceinline__ u64 ffma2(u64 a, u64 b, u64 c) {
    u64 r; asm("fma.rn.f32x2 %0, %1, %2, %3;" : "=l"(r) : "l"(a), "l"(b), "l"(c)); return r;
}
__device__ __forceinline__ u64 fmul2(u64 a, u64 b) {
    u64 r; asm("mul.rn.f32x2 %0, %1, %2;" : "=l"(r) : "l"(a), "l"(b)); return r;
}

// ---------------- Kernel A: merge + warp-shuffle scan + per-tile compacted lists ----------------
__global__ void prep_kernel(const int* __restrict__ text, const int* __restrict__ durs) {
    const int b    = blockIdx.x;
    const int i    = threadIdx.x;
    const int lane = i & 31;
    const int wid  = i >> 5;

    __shared__ float wpart[PWARPS];
    __shared__ int   s_cnt[NTILES];

    if (i < NTILES) s_cnt[i] = 0;

    float d = 0.0f; int tx = 0;
    if (i < NTOK) {
        if (i == 0) { d = (float)durs[b * LSEQ]; tx = text[b * LSEQ]; }
        else {
            d  = (float)(durs[b * LSEQ + 2 * i - 1] + durs[b * LSEQ + 2 * i]);
            tx = text[b * LSEQ + 2 * i - 1];
        }
    }

    // warp-level inclusive scan
    float v = d;
#pragma unroll
    for (int off = 1; off < 32; off <<= 1) {
        float n = __shfl_up_sync(0xffffffffu, v, off);
        if (lane >= off) v += n;
    }
    if (lane == 31) wpart[wid] = v;
    __syncthreads();            // also orders s_cnt zeroing before appends
    if (wid == 0) {
        float s = (lane < PWARPS) ? wpart[lane] : 0.0f;
#pragma unroll
        for (int off = 1; off < 32; off <<= 1) {
            float n = __shfl_up_sync(0xffffffffu, s, off);
            if (lane >= off) s += n;
        }
        if (lane < PWARPS) wpart[lane] = s;
    }
    __syncthreads();
    const float cum = v + (wid > 0 ? wpart[wid - 1] : 0.0f);

    if (i < NTOK) {
        float c    = cum - 0.5f * d;
        float sig  = 0.5f * d + 1e-6f;
        float invs = 1.0f / sig;
        bool  kept = (tx != 0) && (d > 0.0f);
        if (kept) {
            float coef = 0.3989422804014327f * invs;
            // z-cut = 5.5: dropped weights <= 2e-7 vs wsum >= 0.08 -> rel pert <= ~5e-5
            float r = 2.75f * d + 0.51f;
            int k0 = max(0, (int)ceilf((c - r - ((float)TT - 0.5f)) * (1.0f / TT)));
            int k1 = min(NTILES - 1, (int)floorf((c + r - 0.5f) * (1.0f / TT)));
            float4 e = make_float4(c, invs, coef, __int_as_float(tx));
            for (int k = k0; k <= k1; ++k) {
                int s = atomicAdd(&s_cnt[k], 1);   // fast smem atomic
                if (s < KMAX) g_list[b][k][s] = e; // fire-and-forget STG.128
            }
        }
        if (i == NTOK - 1) g_cumend[b] = cum;
    }
    __syncthreads();
    if (i < NTILES) g_cnt[b][i] = min(s_cnt[i], KMAX);
}

// ---------------- Kernel B: persistent pipelined gaussian upsample (PDL) ----------------
__global__ void __launch_bounds__(NTH, 4)
gauss_kernel(const float* __restrict__ emb, float* __restrict__ out) {
    const int tid = threadIdx.x;       // owns embedding cols 2*tid, 2*tid+1

    __shared__ __align__(16) float w_s[KMAX][TT];
    __shared__ float s_c[KMAX], s_is[KMAX], s_cf[KMAX];
    __shared__ int   s_tok[KMAX];
    __shared__ __align__(8) float wsum[TT];
    __shared__ __align__(8) float scale_s[TT];

    const float2* embp = reinterpret_cast<const float2*>(emb);
    float2* outp = reinterpret_cast<float2*>(out);

    // PDL: we were launched while prep was still running; wait for its writes.
    asm volatile("griddepcontrol.wait;" ::: "memory");

    // ---- prefetch first tile's count + list entry ----
    int g = blockIdx.x;
    int cnt_next = 0;
    float4 p_next = make_float4(0.f, 0.f, 0.f, 0.f);
    {
        const int bb = g >> 7, kk = g & (NTILES - 1);
        cnt_next = g_cnt[bb][kk];
        if (tid < KMAX) p_next = g_list[bb][kk][tid];
    }

    for (; g < TOTAL; g += GBLK) {
        const int b   = g >> 7;
        const int t0  = (g & (NTILES - 1)) * TT;
        const int cnt = min(cnt_next, KMAX);
        const float4 p = p_next;

        __syncthreads();    // previous tile fully done with smem
        if (tid < TT) wsum[tid] = 0.0f;
        if (tid < cnt) {
            s_c[tid]   = p.x;
            s_is[tid]  = p.y;
            s_cf[tid]  = p.z;
            s_tok[tid] = __float_as_int(p.w);
        }
        __syncthreads();

        // ---- issue next tile's loads (hidden behind this tile's compute) ----
        {
            const int gn = g + GBLK;
            if (gn < TOTAL) {
                const int bn = gn >> 7, kn = gn & (NTILES - 1);
                cnt_next = g_cnt[bn][kn];
                if (tid < KMAX) p_next = g_list[bn][kn][tid];
            }
        }

        // ---- phase 1: weights -> smem; per-thread register wsum (frame = tid & 15) ----
        {
            const int   myt = tid & (TT - 1);
            const float tm  = (float)(t0 + myt) + 0.5f;
            float wl = 0.0f;
            for (int idx = tid; idx < cnt * TT; idx += NTH) {
                int nl = idx >> 4;
                float z = (tm - s_c[nl]) * s_is[nl];
                float w = s_cf[nl] * __expf(-0.5f * z * z);
                w_s[nl][myt] = w;
                wl += w;
            }
            if (wl != 0.0f) atomicAdd(&wsum[myt], wl);
        }
        __syncthreads();

        if (tid < TT) {
            float tmv = (float)(t0 + tid) + 0.5f;
            scale_s[tid] = (tmv < g_cumend[b]) ? (1.0f / (wsum[tid] + 1e-6f)) : 0.0f;
        }

        // ---- phase 2: packed f32x2 accumulation, double-buffered emb prefetch ----
        u64 accA[TT / 2], accB[TT / 2];
#pragma unroll
        for (int j = 0; j < TT / 2; ++j) { accA[j] = 0ull; accB[j] = 0ull; }

        float2 c0, c1, c2, c3;
        if (cnt >= 4) {
            c0 = embp[s_tok[0] * (EMB / 2) + tid];
            c1 = embp[s_tok[1] * (EMB / 2) + tid];
            c2 = embp[s_tok[2] * (EMB / 2) + tid];
            c3 = embp[s_tok[3] * (EMB / 2) + tid];
        }
        int cs = 0;
        for (; cs + 4 <= cnt; cs += 4) {
            float2 e0 = c0, e1 = c1, e2 = c2, e3 = c3;
            if (cs + 8 <= cnt) {   // prefetch next iteration's rows
                c0 = embp[s_tok[cs + 4] * (EMB / 2) + tid];
                c1 = embp[s_tok[cs + 5] * (EMB / 2) + tid];
                c2 = embp[s_tok[cs + 6] * (EMB / 2) + tid];
                c3 = embp[s_tok[cs + 7] * (EMB / 2) + tid];
            }
#pragma unroll
            for (int u = 0; u < 4; ++u) {
                float2 ev = (u == 0) ? e0 : (u == 1) ? e1 : (u == 2) ? e2 : e3;
                u64 exA = pack2(ev.x, ev.x);
                u64 exB = pack2(ev.y, ev.y);
                const ulonglong2* wp = reinterpret_cast<const ulonglong2*>(w_s[cs + u]);
#pragma unroll
                for (int j = 0; j < TT / 4; ++j) {
                    ulonglong2 wq = wp[j];
                    accA[2 * j + 0] = ffma2(wq.x, exA, accA[2 * j + 0]);
                    accB[2 * j + 0] = ffma2(wq.x, exB, accB[2 * j + 0]);
                    accA[2 * j + 1] = ffma2(wq.y, exA, accA[2 * j + 1]);
                    accB[2 * j + 1] = ffma2(wq.y, exB, accB[2 * j + 1]);
                }
            }
        }
        for (; cs < cnt; ++cs) {
            float2 ev = embp[s_tok[cs] * (EMB / 2) + tid];
            u64 exA = pack2(ev.x, ev.x);
            u64 exB = pack2(ev.y, ev.y);
            const ulonglong2* wp = reinterpret_cast<const ulonglong2*>(w_s[cs]);
#pragma unroll
            for (int j = 0; j < TT / 4; ++j) {
                ulonglong2 wq = wp[j];
                accA[2 * j + 0] = ffma2(wq.x, exA, accA[2 * j + 0]);
                accB[2 * j + 0] = ffma2(wq.x, exB, accB[2 * j + 0]);
                accA[2 * j + 1] = ffma2(wq.y, exA, accA[2 * j + 1]);
                accB[2 * j + 1] = ffma2(wq.y, exB, accB[2 * j + 1]);
            }
        }
        __syncthreads();   // scale_s ready

        // ---- normalize (packed) + store (float2 per frame, coalesced) ----
        size_t base = ((size_t)g * TT) * (EMB / 2) + tid;   // b*TLEN + t0 == g*TT
        const u64* sp = reinterpret_cast<const u64*>(scale_s);
#pragma unroll
        for (int j = 0; j < TT / 2; ++j) {
            u64 s2 = sp[j];                      // (scale[2j], scale[2j+1])
            u64 va = fmul2(accA[j], s2);
            u64 vb = fmul2(accB[j], s2);
            float a0, a1, b0, b1;
            unpack2(va, a0, a1);
            unpack2(vb, b0, b1);
            outp[base + (size_t)(2 * j)     * (EMB / 2)] = make_float2(a0, b0);
            outp[base + (size_t)(2 * j + 1) * (EMB / 2)] = make_float2(a1, b1);
        }
    }
}

extern "C" void kernel_launch(void* const* d_in, const int* in_sizes, int n_in,
                              void* d_out, int out_size) {
    const int*   text = (const int*)d_in[0];
    const int*   durs = (const int*)d_in[1];
    const float* emb  = (const float*)d_in[2];
    float* out = (float*)d_out;

    prep_kernel<<<BATCH, 544>>>(text, durs);

    // PDL launch: gauss starts while prep drains; griddepcontrol.wait gates the reads
    cudaLaunchConfig_t cfg = {};
    cfg.gridDim  = dim3(GBLK, 1, 1);
    cfg.blockDim = dim3(NTH, 1, 1);
    cfg.dynamicSmemBytes = 0;
    cfg.stream = 0;
    cudaLaunchAttribute attr[1];
    attr[0].id = cudaLaunchAttributeProgrammaticStreamSerialization;
    attr[0].val.programmaticStreamSerializationAllowed = 1;
    cfg.attrs = attr;
    cfg.numAttrs = 1;
    cudaLaunchKernelEx(&cfg, gauss_kernel, emb, out);
}

// round 15
// speedup vs baseline: 1.3679x; 1.0569x over previous
#include <cuda_runtime.h>
#include <cuda_bf16.h>

#define BATCH  32
#define LSEQ   1025
#define NTOK   513
#define TLEN   2048
#define EMB    384
#define TT     16            // frames per tile
#define NTILES (TLEN / TT)   // 128
#define NTH    192           // threads per block; each owns 2 embedding cols
#define KMAX   64            // max tokens per tile list
#define PWARPS 17            // prep warps (544 threads)
#define GBLK   592           // persistent grid: 4 CTAs/SM x 148 SMs
#define TOTAL  (BATCH * NTILES)

using u64 = unsigned long long;

__device__ float4 g_list[BATCH][NTILES][KMAX]; // {center, 1/sig, coef, row offset (tok*EMB/2) bits}
__device__ int    g_cnt[BATCH][NTILES];
__device__ float  g_cumend[BATCH];

__device__ __forceinline__ u64 pack2(float lo, float hi) {
    u64 r; asm("mov.b64 %0, {%1,%2};" : "=l"(r) : "f"(lo), "f"(hi)); return r;
}
__device__ __forceinline__ void unpack2(u64 v, float& lo, float& hi) {
    asm("mov.b64 {%0,%1}, %2;" : "=f"(lo), "=f"(hi) : "l"(v));
}
__device__ __forceinline__ u64 ffma2(u64 a, u64 b, u64 c) {
    u64 r; asm("fma.rn.f32x2 %0, %1, %2, %3;" : "=l"(r) : "l"(a), "l"(b), "l"(c)); return r;
}
__device__ __forceinline__ u64 fmul2(u64 a, u64 b) {
    u64 r; asm("mul.rn.f32x2 %0, %1, %2;" : "=l"(r) : "l"(a), "l"(b)); return r;
}

// ---------------- Kernel A: merge + warp-shuffle scan + per-tile compacted lists ----------------
__global__ void prep_kernel(const int* __restrict__ text, const int* __restrict__ durs) {
    const int b    = blockIdx.x;
    const int i    = threadIdx.x;
    const int lane = i & 31;
    const int wid  = i >> 5;

    __shared__ float wpart[PWARPS];
    __shared__ int   s_cnt[NTILES];

    if (i < NTILES) s_cnt[i] = 0;

    float d = 0.0f; int tx = 0;
    if (i < NTOK) {
        if (i == 0) { d = (float)durs[b * LSEQ]; tx = text[b * LSEQ]; }
        else {
            d  = (float)(durs[b * LSEQ + 2 * i - 1] + durs[b * LSEQ + 2 * i]);
            tx = text[b * LSEQ + 2 * i - 1];
        }
    }

    // warp-level inclusive scan
    float v = d;
#pragma unroll
    for (int off = 1; off < 32; off <<= 1) {
        float n = __shfl_up_sync(0xffffffffu, v, off);
        if (lane >= off) v += n;
    }
    if (lane == 31) wpart[wid] = v;
    __syncthreads();            // also orders s_cnt zeroing before appends
    if (wid == 0) {
        float s = (lane < PWARPS) ? wpart[lane] : 0.0f;
#pragma unroll
        for (int off = 1; off < 32; off <<= 1) {
            float n = __shfl_up_sync(0xffffffffu, s, off);
            if (lane >= off) s += n;
        }
        if (lane < PWARPS) wpart[lane] = s;
    }
    __syncthreads();
    const float cum = v + (wid > 0 ? wpart[wid - 1] : 0.0f);

    if (i < NTOK) {
        float c    = cum - 0.5f * d;
        float sig  = 0.5f * d + 1e-6f;
        float invs = 1.0f / sig;
        bool  kept = (tx != 0) && (d > 0.0f);
        if (kept) {
            float coef = 0.3989422804014327f * invs;
            // z-cut = 5.5: dropped weights <= 2e-7 vs wsum >= 0.08 -> rel pert <= ~5e-5
            float r = 2.75f * d + 0.51f;
            int k0 = max(0, (int)ceilf((c - r - ((float)TT - 0.5f)) * (1.0f / TT)));
            int k1 = min(NTILES - 1, (int)floorf((c + r - 0.5f) * (1.0f / TT)));
            float4 e = make_float4(c, invs, coef, __int_as_float(tx * (EMB / 2)));
            for (int k = k0; k <= k1; ++k) {
                int s = atomicAdd(&s_cnt[k], 1);   // fast smem atomic
                if (s < KMAX) g_list[b][k][s] = e; // fire-and-forget STG.128
            }
        }
        if (i == NTOK - 1) g_cumend[b] = cum;
    }
    __syncthreads();
    if (i < NTILES) g_cnt[b][i] = min(s_cnt[i], KMAX);
}

// ---------------- Kernel B: persistent pipelined gaussian upsample (PDL) ----------------
__global__ void __launch_bounds__(NTH, 4)
gauss_kernel(const float* __restrict__ emb, float* __restrict__ out) {
    const int tid = threadIdx.x;       // owns embedding cols 2*tid, 2*tid+1

    __shared__ __align__(16) float w_s[KMAX][TT];
    __shared__ float s_c[KMAX], s_is[KMAX], s_cf[KMAX];
    __shared__ int   s_tok[KMAX];      // pre-multiplied row offsets (tok * EMB/2)
    __shared__ __align__(8) float wsum[TT];
    __shared__ __align__(8) float scale_s[TT];

    const float2* embp = reinterpret_cast<const float2*>(emb);
    float2* outp = reinterpret_cast<float2*>(out);

    // PDL: we were launched while prep was still running; wait for its writes.
    asm volatile("griddepcontrol.wait;" ::: "memory");

    // ---- prefetch first tile's count + list entry ----
    int g = blockIdx.x;
    int cnt_next = 0;
    float4 p_next = make_float4(0.f, 0.f, 0.f, 0.f);
    {
        const int bb = g >> 7, kk = g & (NTILES - 1);
        cnt_next = g_cnt[bb][kk];
        if (tid < KMAX) p_next = g_list[bb][kk][tid];
    }

    for (; g < TOTAL; g += GBLK) {
        const int b   = g >> 7;
        const int t0  = (g & (NTILES - 1)) * TT;
        const int cnt = min(cnt_next, KMAX);
        const float4 p = p_next;

        __syncthreads();    // previous tile fully done with smem
        if (tid < TT) wsum[tid] = 0.0f;
        if (tid < cnt) {
            s_c[tid]   = p.x;
            s_is[tid]  = p.y;
            s_cf[tid]  = p.z;
            s_tok[tid] = __float_as_int(p.w);
        }
        __syncthreads();

        // ---- issue next tile's loads (hidden behind this tile's compute) ----
        {
            const int gn = g + GBLK;
            if (gn < TOTAL) {
                const int bn = gn >> 7, kn = gn & (NTILES - 1);
                cnt_next = g_cnt[bn][kn];
                if (tid < KMAX) p_next = g_list[bn][kn][tid];
            }
        }

        // ---- phase 1: weights -> smem; per-thread register wsum (frame = tid & 15) ----
        {
            const int   myt = tid & (TT - 1);
            const float tm  = (float)(t0 + myt) + 0.5f;
            float wl = 0.0f;
            for (int idx = tid; idx < cnt * TT; idx += NTH) {
                int nl = idx >> 4;
                float z = (tm - s_c[nl]) * s_is[nl];
                float w = s_cf[nl] * __expf(-0.5f * z * z);
                w_s[nl][myt] = w;
                wl += w;
            }
            if (wl != 0.0f) atomicAdd(&wsum[myt], wl);
        }
        __syncthreads();

        if (tid < TT) {
            float tmv = (float)(t0 + tid) + 0.5f;
            scale_s[tid] = (tmv < g_cumend[b]) ? (1.0f / (wsum[tid] + 1e-6f)) : 0.0f;
        }

        // ---- phase 2: packed f32x2 accumulation, 4-token unroll, MLP=4 ----
        u64 accA[TT / 2], accB[TT / 2];
#pragma unroll
        for (int j = 0; j < TT / 2; ++j) { accA[j] = 0ull; accB[j] = 0ull; }

        int cs = 0;
        for (; cs + 4 <= cnt; cs += 4) {
            float2 e0 = embp[s_tok[cs + 0] + tid];
            float2 e1 = embp[s_tok[cs + 1] + tid];
            float2 e2 = embp[s_tok[cs + 2] + tid];
            float2 e3 = embp[s_tok[cs + 3] + tid];
#pragma unroll
            for (int u = 0; u < 4; ++u) {
                float2 ev = (u == 0) ? e0 : (u == 1) ? e1 : (u == 2) ? e2 : e3;
                u64 exA = pack2(ev.x, ev.x);
                u64 exB = pack2(ev.y, ev.y);
                const ulonglong2* wp = reinterpret_cast<const ulonglong2*>(w_s[cs + u]);
#pragma unroll
                for (int j = 0; j < TT / 4; ++j) {
                    ulonglong2 wq = wp[j];
                    accA[2 * j + 0] = ffma2(wq.x, exA, accA[2 * j + 0]);
                    accB[2 * j + 0] = ffma2(wq.x, exB, accB[2 * j + 0]);
                    accA[2 * j + 1] = ffma2(wq.y, exA, accA[2 * j + 1]);
                    accB[2 * j + 1] = ffma2(wq.y, exB, accB[2 * j + 1]);
                }
            }
        }
        for (; cs < cnt; ++cs) {
            float2 ev = embp[s_tok[cs] + tid];
            u64 exA = pack2(ev.x, ev.x);
            u64 exB = pack2(ev.y, ev.y);
            const ulonglong2* wp = reinterpret_cast<const ulonglong2*>(w_s[cs]);
#pragma unroll
            for (int j = 0; j < TT / 4; ++j) {
                ulonglong2 wq = wp[j];
                accA[2 * j + 0] = ffma2(wq.x, exA, accA[2 * j + 0]);
                accB[2 * j + 0] = ffma2(wq.x, exB, accB[2 * j + 0]);
                accA[2 * j + 1] = ffma2(wq.y, exA, accA[2 * j + 1]);
                accB[2 * j + 1] = ffma2(wq.y, exB, accB[2 * j + 1]);
            }
        }
        __syncthreads();   // scale_s ready

        // ---- normalize (packed) + store (float2 per frame, coalesced) ----
        size_t base = ((size_t)g * TT) * (EMB / 2) + tid;   // b*TLEN + t0 == g*TT
        const u64* sp = reinterpret_cast<const u64*>(scale_s);
#pragma unroll
        for (int j = 0; j < TT / 2; ++j) {
            u64 s2 = sp[j];                      // (scale[2j], scale[2j+1])
            u64 va = fmul2(accA[j], s2);
            u64 vb = fmul2(accB[j], s2);
            float a0, a1, b0, b1;
            unpack2(va, a0, a1);
            unpack2(vb, b0, b1);
            outp[base + (size_t)(2 * j)     * (EMB / 2)] = make_float2(a0, b0);
            outp[base + (size_t)(2 * j + 1) * (EMB / 2)] = make_float2(a1, b1);
        }
    }
}

extern "C" void kernel_launch(void* const* d_in, const int* in_sizes, int n_in,
                              void* d_out, int out_size) {
    const int*   text = (const int*)d_in[0];
    const int*   durs = (const int*)d_in[1];
    const float* emb  = (const float*)d_in[2];
    float* out = (float*)d_out;

    prep_kernel<<<BATCH, 544>>>(text, durs);

    // PDL launch: gauss starts while prep drains; griddepcontrol.wait gates the reads
    cudaLaunchConfig_t cfg = {};
    cfg.gridDim  = dim3(GBLK, 1, 1);
    cfg.blockDim = dim3(NTH, 1, 1);
    cfg.dynamicSmemBytes = 0;
    cfg.stream = 0;
    cudaLaunchAttribute attr[1];
    attr[0].id = cudaLaunchAttributeProgrammaticStreamSerialization;
    attr[0].val.programmaticStreamSerializationAllowed = 1;
    cfg.attrs = attr;
    cfg.numAttrs = 1;
    cudaLaunchKernelEx(&cfg, gauss_kernel, emb, out);
}